// round 2
// baseline (speedup 1.0000x reference)
#include <cuda_runtime.h>
#include <cuda_bf16.h>
#include <cstdint>

// out[B,N] = x[B,K] @ w[K,N] + bias[N]
#define BATCH 4096
#define KDIM  4096
#define NDIM  4096

#define TM 256
#define TN 128
#define KC 64          // K elements per stage (128 bytes bf16 per row)
#define STAGES 3
#define THREADS 512    // 16 warps: 4 (M) x 4 (N), warp tile 64x32
#define KPRIME_ITERS 192   // 3*4096 / KC

// ---------------- scratch (device globals: allocation-free) ----------------
__device__ __nv_bfloat16 g_xh[(size_t)BATCH * KDIM];
__device__ __nv_bfloat16 g_xl[(size_t)BATCH * KDIM];
__device__ __nv_bfloat16 g_wh[(size_t)NDIM * KDIM];   // transposed: [n][k]
__device__ __nv_bfloat16 g_wl[(size_t)NDIM * KDIM];   // transposed: [n][k]

// SMEM stage layout: A tile 256 rows x 128B, B tile 128 rows x 128B
#define STAGE_BYTES (TM * 128 + TN * 128)   // 49152
#define SMEM_TOTAL  (STAGES * STAGE_BYTES)  // 147456

__device__ __forceinline__ uint32_t smem_u32(const void* p) {
    uint32_t a;
    asm("{ .reg .u64 t; cvta.to.shared.u64 t, %1; cvt.u32.u64 %0, t; }"
        : "=r"(a) : "l"(p));
    return a;
}

__device__ __forceinline__ void cp_async16(uint32_t smaddr, const void* gptr) {
    asm volatile("cp.async.cg.shared.global [%0], [%1], 16;\n"
                 :: "r"(smaddr), "l"(gptr));
}
#define CP_COMMIT() asm volatile("cp.async.commit_group;\n" ::: "memory")
#define CP_WAIT1()  asm volatile("cp.async.wait_group 1;\n" ::: "memory")

__device__ __forceinline__ void ldsm_x4(uint32_t addr, uint32_t& r0, uint32_t& r1,
                                        uint32_t& r2, uint32_t& r3) {
    asm volatile("ldmatrix.sync.aligned.m8n8.x4.shared.b16 {%0,%1,%2,%3}, [%4];"
                 : "=r"(r0), "=r"(r1), "=r"(r2), "=r"(r3) : "r"(addr));
}

__device__ __forceinline__ void mma_16816(float* c, const uint32_t* a,
                                          uint32_t b0, uint32_t b1) {
    asm volatile(
        "mma.sync.aligned.m16n8k16.row.col.f32.bf16.bf16.f32 "
        "{%0,%1,%2,%3}, {%4,%5,%6,%7}, {%8,%9}, {%0,%1,%2,%3};"
        : "+f"(c[0]), "+f"(c[1]), "+f"(c[2]), "+f"(c[3])
        : "r"(a[0]), "r"(a[1]), "r"(a[2]), "r"(a[3]), "r"(b0), "r"(b1));
}

// ---------------- prepass 1: split x into bf16 hi/lo ----------------
__global__ void __launch_bounds__(256) split_x_kernel(const float4* __restrict__ x) {
    size_t i = (size_t)blockIdx.x * blockDim.x + threadIdx.x;  // 4 floats / thread
    float4 v = x[i];
    __nv_bfloat16 h0 = __float2bfloat16(v.x);
    __nv_bfloat16 h1 = __float2bfloat16(v.y);
    __nv_bfloat16 h2 = __float2bfloat16(v.z);
    __nv_bfloat16 h3 = __float2bfloat16(v.w);
    __nv_bfloat16 l0 = __float2bfloat16(v.x - __bfloat162float(h0));
    __nv_bfloat16 l1 = __float2bfloat16(v.y - __bfloat162float(h1));
    __nv_bfloat16 l2 = __float2bfloat16(v.z - __bfloat162float(h2));
    __nv_bfloat16 l3 = __float2bfloat16(v.w - __bfloat162float(h3));
    __nv_bfloat162* xh = reinterpret_cast<__nv_bfloat162*>(g_xh);
    __nv_bfloat162* xl = reinterpret_cast<__nv_bfloat162*>(g_xl);
    xh[2 * i]     = __nv_bfloat162(h0, h1);
    xh[2 * i + 1] = __nv_bfloat162(h2, h3);
    xl[2 * i]     = __nv_bfloat162(l0, l1);
    xl[2 * i + 1] = __nv_bfloat162(l2, l3);
}

// ---------------- prepass 2: split + transpose w -> [n][k] bf16 hi/lo -------
__global__ void __launch_bounds__(256) split_transpose_w_kernel(const float* __restrict__ w) {
    __shared__ float tile[32][33];
    int o0 = blockIdx.x * 32;  // output (N) tile
    int i0 = blockIdx.y * 32;  // input (K) tile
    int tx = threadIdx.x, ty = threadIdx.y;
    #pragma unroll
    for (int r = ty; r < 32; r += 8)
        tile[r][tx] = w[(size_t)(i0 + r) * NDIM + o0 + tx];
    __syncthreads();
    #pragma unroll
    for (int r = ty; r < 32; r += 8) {
        float f = tile[tx][r];  // = w[i0+tx][o0+r]
        __nv_bfloat16 hi = __float2bfloat16(f);
        __nv_bfloat16 lo = __float2bfloat16(f - __bfloat162float(hi));
        size_t dst = (size_t)(o0 + r) * KDIM + i0 + tx;
        g_wh[dst] = hi;
        g_wl[dst] = lo;
    }
}

// ---------------- producer: fill one pipeline stage ----------------
__device__ __forceinline__ void load_stage(uint32_t sb, int stage, int it,
                                           int m0, int n0, int tid) {
    // region: 0 -> (xh, wh), 1 -> (xl, wh), 2 -> (xh, wl)
    int r = it >> 6;
    const __nv_bfloat16* Asrc = (r == 1) ? g_xl : g_xh;
    const __nv_bfloat16* Bsrc = (r == 2) ? g_wl : g_wh;
    int k0 = (it & 63) * KC;
    uint32_t sa = sb + stage * STAGE_BYTES;
    uint32_t sbB = sa + TM * 128;
    // 384 rows * 8 segs of 16B = 3072 cp.async; 6 per thread
    #pragma unroll
    for (int j = 0; j < 6; ++j) {
        int t = tid + j * THREADS;
        int row = t >> 3;
        int seg = t & 7;
        if (row < TM) {
            const __nv_bfloat16* gp = Asrc + (size_t)(m0 + row) * KDIM + k0 + seg * 8;
            uint32_t sm = sa + row * 128 + ((seg ^ (row & 7)) << 4);
            cp_async16(sm, gp);
        } else {
            int rb = row - TM;
            const __nv_bfloat16* gp = Bsrc + (size_t)(n0 + rb) * KDIM + k0 + seg * 8;
            uint32_t sm = sbB + rb * 128 + ((seg ^ (rb & 7)) << 4);
            cp_async16(sm, gp);
        }
    }
}

// ---------------- main GEMM: bf16x3 via mma.sync, cp.async pipeline ----------
__global__ void __launch_bounds__(THREADS, 1)
gemm_bf16x3_kernel(const float* __restrict__ bias, float* __restrict__ out) {
    extern __shared__ char smem[];
    uint32_t sb = smem_u32(smem);
    int tid = threadIdx.x;
    int lane = tid & 31;
    int wid = tid >> 5;
    int wm = wid & 3;       // M warp group (64 rows)
    int wn = wid >> 2;      // N warp group (32 cols)
    int m0 = blockIdx.y * TM;
    int n0 = blockIdx.x * TN;

    float acc[4][4][4];     // [mt 16-row tile][n8 tile][c0..c3]
    #pragma unroll
    for (int i = 0; i < 4; ++i)
        #pragma unroll
        for (int j = 0; j < 4; ++j)
            #pragma unroll
            for (int k = 0; k < 4; ++k) acc[i][j][k] = 0.f;

    // prologue: stages 0 and 1
    load_stage(sb, 0, 0, m0, n0, tid); CP_COMMIT();
    load_stage(sb, 1, 1, m0, n0, tid); CP_COMMIT();

    // lane row bases for ldmatrix x4 (lanes 0-15 pick rows, lanes>>4 picks k-half)
    int la = (lane & 15);
    int khalf = lane >> 4;

    for (int it = 0; it < KPRIME_ITERS; ++it) {
        CP_WAIT1();
        __syncthreads();

        if (it + 2 < KPRIME_ITERS)
            load_stage(sb, (it + 2) % STAGES, it + 2, m0, n0, tid);
        CP_COMMIT();

        uint32_t sa = sb + (it % STAGES) * STAGE_BYTES;
        uint32_t sB = sa + TM * 128;

        #pragma unroll
        for (int ks = 0; ks < 4; ++ks) {
            int seg = 2 * ks + khalf;
            // A fragments: 4 m16 tiles
            uint32_t af[4][4];
            #pragma unroll
            for (int mt = 0; mt < 4; ++mt) {
                int row = wm * 64 + mt * 16 + la;
                uint32_t addr = sa + row * 128 + ((seg ^ (row & 7)) << 4);
                ldsm_x4(addr, af[mt][0], af[mt][1], af[mt][2], af[mt][3]);
            }
            // B fragments: 2 x4 loads cover 4 n8 tiles
            uint32_t bf[4][2];
            {
                int row = wn * 32 + la;
                uint32_t addr = sB + row * 128 + ((seg ^ (row & 7)) << 4);
                uint32_t r0, r1, r2, r3;
                ldsm_x4(addr, r0, r1, r2, r3);
                bf[0][0] = r0; bf[0][1] = r2;
                bf[1][0] = r1; bf[1][1] = r3;
                row = wn * 32 + 16 + la;
                addr = sB + row * 128 + ((seg ^ (row & 7)) << 4);
                ldsm_x4(addr, r0, r1, r2, r3);
                bf[2][0] = r0; bf[2][1] = r2;
                bf[3][0] = r1; bf[3][1] = r3;
            }
            #pragma unroll
            for (int mt = 0; mt < 4; ++mt)
                #pragma unroll
                for (int nb = 0; nb < 4; ++nb)
                    mma_16816(acc[mt][nb], af[mt], bf[nb][0], bf[nb][1]);
        }
    }

    // ---------------- epilogue: bias + store ----------------
    float2 bv[4];
    #pragma unroll
    for (int nb = 0; nb < 4; ++nb) {
        int col = n0 + wn * 32 + nb * 8 + (lane & 3) * 2;
        bv[nb] = *reinterpret_cast<const float2*>(bias + col);
    }
    #pragma unroll
    for (int mt = 0; mt < 4; ++mt) {
        int gr = m0 + wm * 64 + mt * 16 + (lane >> 2);
        float* r0p = out + (size_t)gr * NDIM;
        float* r1p = r0p + 8 * (size_t)NDIM;
        #pragma unroll
        for (int nb = 0; nb < 4; ++nb) {
            int col = n0 + wn * 32 + nb * 8 + (lane & 3) * 2;
            float2 v0 = make_float2(acc[mt][nb][0] + bv[nb].x,
                                    acc[mt][nb][1] + bv[nb].y);
            float2 v1 = make_float2(acc[mt][nb][2] + bv[nb].x,
                                    acc[mt][nb][3] + bv[nb].y);
            *reinterpret_cast<float2*>(r0p + col) = v0;
            *reinterpret_cast<float2*>(r1p + col) = v1;
        }
    }
}

// ---------------- launch ----------------
extern "C" void kernel_launch(void* const* d_in, const int* in_sizes, int n_in,
                              void* d_out, int out_size) {
    const float* x    = (const float*)d_in[0];
    const float* w    = (const float*)d_in[1];
    const float* bias = (const float*)d_in[2];
    float* out = (float*)d_out;

    split_x_kernel<<<(BATCH * (size_t)KDIM / 4) / 256, 256>>>((const float4*)x);
    split_transpose_w_kernel<<<dim3(NDIM / 32, KDIM / 32), dim3(32, 8)>>>(w);

    cudaFuncSetAttribute(gemm_bf16x3_kernel,
                         cudaFuncAttributeMaxDynamicSharedMemorySize, SMEM_TOTAL);
    gemm_bf16x3_kernel<<<dim3(NDIM / TN, BATCH / TM), THREADS, SMEM_TOTAL>>>(bias, out);
}

// round 3
// speedup vs baseline: 2.8633x; 2.8633x over previous
#include <cuda_runtime.h>
#include <cuda_fp16.h>
#include <cstdint>

// out[B,N] = x[B,K] @ w[K,N] + bias[N]
// Strategy: single-pass fp16 HMMA (m16n8k16, f32 accumulate).
// fp16 conversion error ~2^-12/elem -> norm rel_err ~2e-4 << 1e-3 threshold.
#define BATCH 4096
#define KDIM  4096
#define NDIM  4096

#define TM 256
#define TN 128
#define KC 64          // K elements per stage (128 bytes fp16 per row)
#define STAGES 3
#define THREADS 512    // 16 warps: 4 (M) x 4 (N), warp tile 64x32
#define K_ITERS (KDIM / KC)   // 64

// ---------------- scratch (device globals: allocation-free) ----------------
__device__ __half g_x[(size_t)BATCH * KDIM];
__device__ __half g_w[(size_t)NDIM * KDIM];   // transposed: [n][k]

// SMEM stage layout: A tile 256 rows x 128B, B tile 128 rows x 128B
#define STAGE_BYTES (TM * 128 + TN * 128)   // 49152
#define SMEM_TOTAL  (STAGES * STAGE_BYTES)  // 147456

__device__ __forceinline__ uint32_t smem_u32(const void* p) {
    uint32_t a;
    asm("{ .reg .u64 t; cvta.to.shared.u64 t, %1; cvt.u32.u64 %0, t; }"
        : "=r"(a) : "l"(p));
    return a;
}

__device__ __forceinline__ void cp_async16(uint32_t smaddr, const void* gptr) {
    asm volatile("cp.async.cg.shared.global [%0], [%1], 16;\n"
                 :: "r"(smaddr), "l"(gptr));
}
#define CP_COMMIT() asm volatile("cp.async.commit_group;\n" ::: "memory")
#define CP_WAIT1()  asm volatile("cp.async.wait_group 1;\n" ::: "memory")

__device__ __forceinline__ void ldsm_x4(uint32_t addr, uint32_t& r0, uint32_t& r1,
                                        uint32_t& r2, uint32_t& r3) {
    asm volatile("ldmatrix.sync.aligned.m8n8.x4.shared.b16 {%0,%1,%2,%3}, [%4];"
                 : "=r"(r0), "=r"(r1), "=r"(r2), "=r"(r3) : "r"(addr));
}

__device__ __forceinline__ void mma_16816(float* c, const uint32_t* a,
                                          uint32_t b0, uint32_t b1) {
    asm volatile(
        "mma.sync.aligned.m16n8k16.row.col.f32.f16.f16.f32 "
        "{%0,%1,%2,%3}, {%4,%5,%6,%7}, {%8,%9}, {%0,%1,%2,%3};"
        : "+f"(c[0]), "+f"(c[1]), "+f"(c[2]), "+f"(c[3])
        : "r"(a[0]), "r"(a[1]), "r"(a[2]), "r"(a[3]), "r"(b0), "r"(b1));
}

// ---------------- prepass 1: convert x -> fp16 ----------------
__global__ void __launch_bounds__(256) conv_x_kernel(const float4* __restrict__ x) {
    size_t i = (size_t)blockIdx.x * blockDim.x + threadIdx.x;  // 4 floats / thread
    float4 v = x[i];
    __half2* xp = reinterpret_cast<__half2*>(g_x);
    xp[2 * i]     = __floats2half2_rn(v.x, v.y);
    xp[2 * i + 1] = __floats2half2_rn(v.z, v.w);
}

// ---------------- prepass 2: transpose + convert w -> [n][k] fp16 ----------
__global__ void __launch_bounds__(256) conv_transpose_w_kernel(const float* __restrict__ w) {
    __shared__ float tile[32][33];
    int o0 = blockIdx.x * 32;  // output (N) tile
    int i0 = blockIdx.y * 32;  // input (K) tile
    int tx = threadIdx.x, ty = threadIdx.y;
    #pragma unroll
    for (int r = ty; r < 32; r += 8)
        tile[r][tx] = w[(size_t)(i0 + r) * NDIM + o0 + tx];
    __syncthreads();
    #pragma unroll
    for (int r = ty; r < 32; r += 8) {
        float f = tile[tx][r];  // = w[i0+tx][o0+r]
        g_w[(size_t)(o0 + r) * KDIM + i0 + tx] = __float2half_rn(f);
    }
}

// ---------------- producer: fill one pipeline stage ----------------
__device__ __forceinline__ void load_stage(uint32_t sb, int stage, int it,
                                           int m0, int n0, int tid) {
    int k0 = it * KC;
    uint32_t sa = sb + stage * STAGE_BYTES;
    uint32_t sbB = sa + TM * 128;
    // 384 rows * 8 segs of 16B = 3072 cp.async; 6 per thread
    #pragma unroll
    for (int j = 0; j < 6; ++j) {
        int t = tid + j * THREADS;
        int row = t >> 3;
        int seg = t & 7;
        if (row < TM) {
            const __half* gp = g_x + (size_t)(m0 + row) * KDIM + k0 + seg * 8;
            uint32_t sm = sa + row * 128 + ((seg ^ (row & 7)) << 4);
            cp_async16(sm, gp);
        } else {
            int rb = row - TM;
            const __half* gp = g_w + (size_t)(n0 + rb) * KDIM + k0 + seg * 8;
            uint32_t sm = sbB + rb * 128 + ((seg ^ (rb & 7)) << 4);
            cp_async16(sm, gp);
        }
    }
}

// ---------------- main GEMM: fp16 mma.sync, cp.async pipeline ----------
__global__ void __launch_bounds__(THREADS, 1)
gemm_fp16_kernel(const float* __restrict__ bias, float* __restrict__ out) {
    extern __shared__ char smem[];
    uint32_t sb = smem_u32(smem);
    int tid = threadIdx.x;
    int lane = tid & 31;
    int wid = tid >> 5;
    int wm = wid & 3;       // M warp group (64 rows)
    int wn = wid >> 2;      // N warp group (32 cols)
    int m0 = blockIdx.y * TM;
    int n0 = blockIdx.x * TN;

    float acc[4][4][4];     // [mt 16-row tile][n8 tile][c0..c3]
    #pragma unroll
    for (int i = 0; i < 4; ++i)
        #pragma unroll
        for (int j = 0; j < 4; ++j)
            #pragma unroll
            for (int k = 0; k < 4; ++k) acc[i][j][k] = 0.f;

    // prologue: stages 0 and 1
    load_stage(sb, 0, 0, m0, n0, tid); CP_COMMIT();
    load_stage(sb, 1, 1, m0, n0, tid); CP_COMMIT();

    // lane row bases for ldmatrix x4 (lanes 0-15 pick rows, lane>>4 picks k-half)
    int la = (lane & 15);
    int khalf = lane >> 4;

    for (int it = 0; it < K_ITERS; ++it) {
        CP_WAIT1();
        __syncthreads();

        if (it + 2 < K_ITERS)
            load_stage(sb, (it + 2) % STAGES, it + 2, m0, n0, tid);
        CP_COMMIT();

        uint32_t sa = sb + (it % STAGES) * STAGE_BYTES;
        uint32_t sB = sa + TM * 128;

        #pragma unroll
        for (int ks = 0; ks < 4; ++ks) {
            int seg = 2 * ks + khalf;
            // A fragments: 4 m16 tiles
            uint32_t af[4][4];
            #pragma unroll
            for (int mt = 0; mt < 4; ++mt) {
                int row = wm * 64 + mt * 16 + la;
                uint32_t addr = sa + row * 128 + ((seg ^ (row & 7)) << 4);
                ldsm_x4(addr, af[mt][0], af[mt][1], af[mt][2], af[mt][3]);
            }
            // B fragments: 2 x4 loads cover 4 n8 tiles
            uint32_t bf[4][2];
            {
                int row = wn * 32 + la;
                uint32_t addr = sB + row * 128 + ((seg ^ (row & 7)) << 4);
                uint32_t r0, r1, r2, r3;
                ldsm_x4(addr, r0, r1, r2, r3);
                bf[0][0] = r0; bf[0][1] = r2;
                bf[1][0] = r1; bf[1][1] = r3;
                row = wn * 32 + 16 + la;
                addr = sB + row * 128 + ((seg ^ (row & 7)) << 4);
                ldsm_x4(addr, r0, r1, r2, r3);
                bf[2][0] = r0; bf[2][1] = r2;
                bf[3][0] = r1; bf[3][1] = r3;
            }
            #pragma unroll
            for (int mt = 0; mt < 4; ++mt)
                #pragma unroll
                for (int nb = 0; nb < 4; ++nb)
                    mma_16816(acc[mt][nb], af[mt], bf[nb][0], bf[nb][1]);
        }
    }

    // ---------------- epilogue: bias + store ----------------
    float2 bv[4];
    #pragma unroll
    for (int nb = 0; nb < 4; ++nb) {
        int col = n0 + wn * 32 + nb * 8 + (lane & 3) * 2;
        bv[nb] = *reinterpret_cast<const float2*>(bias + col);
    }
    #pragma unroll
    for (int mt = 0; mt < 4; ++mt) {
        int gr = m0 + wm * 64 + mt * 16 + (lane >> 2);
        float* r0p = out + (size_t)gr * NDIM;
        float* r1p = r0p + 8 * (size_t)NDIM;
        #pragma unroll
        for (int nb = 0; nb < 4; ++nb) {
            int col = n0 + wn * 32 + nb * 8 + (lane & 3) * 2;
            float2 v0 = make_float2(acc[mt][nb][0] + bv[nb].x,
                                    acc[mt][nb][1] + bv[nb].y);
            float2 v1 = make_float2(acc[mt][nb][2] + bv[nb].x,
                                    acc[mt][nb][3] + bv[nb].y);
            *reinterpret_cast<float2*>(r0p + col) = v0;
            *reinterpret_cast<float2*>(r1p + col) = v1;
        }
    }
}

// ---------------- launch ----------------
extern "C" void kernel_launch(void* const* d_in, const int* in_sizes, int n_in,
                              void* d_out, int out_size) {
    const float* x    = (const float*)d_in[0];
    const float* w    = (const float*)d_in[1];
    const float* bias = (const float*)d_in[2];
    float* out = (float*)d_out;

    conv_x_kernel<<<(BATCH * (size_t)KDIM / 4) / 256, 256>>>((const float4*)x);
    conv_transpose_w_kernel<<<dim3(NDIM / 32, KDIM / 32), dim3(32, 8)>>>(w);

    cudaFuncSetAttribute(gemm_fp16_kernel,
                         cudaFuncAttributeMaxDynamicSharedMemorySize, SMEM_TOTAL);
    gemm_fp16_kernel<<<dim3(NDIM / TN, BATCH / TM), THREADS, SMEM_TOTAL>>>(bias, out);
}

// round 4
// speedup vs baseline: 3.2211x; 1.1249x over previous
#include <cuda_runtime.h>
#include <cuda_fp16.h>
#include <cstdint>

// out[B,N] = x[B,K] @ w[K,N] + bias[N]
// Single-pass fp16 HMMA (m16n8k16, f32 accumulate), 2 CTAs/SM.
#define BATCH 4096
#define KDIM  4096
#define NDIM  4096

#define TM 128
#define TN 128
#define KC 64          // K elements per stage (128 bytes fp16 per row)
#define STAGES 3
#define THREADS 256    // 8 warps: 2 (M) x 4 (N), warp tile 64x32
#define K_ITERS (KDIM / KC)   // 64

// ---------------- scratch (device globals: allocation-free) ----------------
__device__ __half g_x[(size_t)BATCH * KDIM];
__device__ __half g_w[(size_t)NDIM * KDIM];   // transposed: [n][k]

// SMEM stage layout: A tile 128 rows x 128B, B tile 128 rows x 128B
#define STAGE_BYTES (TM * 128 + TN * 128)   // 32768
#define SMEM_TOTAL  (STAGES * STAGE_BYTES)  // 98304  (x2 CTAs = 192KB/SM)

__device__ __forceinline__ uint32_t smem_u32(const void* p) {
    uint32_t a;
    asm("{ .reg .u64 t; cvta.to.shared.u64 t, %1; cvt.u32.u64 %0, t; }"
        : "=r"(a) : "l"(p));
    return a;
}

__device__ __forceinline__ void cp_async16(uint32_t smaddr, const void* gptr) {
    asm volatile("cp.async.cg.shared.global [%0], [%1], 16;\n"
                 :: "r"(smaddr), "l"(gptr));
}
#define CP_COMMIT() asm volatile("cp.async.commit_group;\n" ::: "memory")
#define CP_WAIT1()  asm volatile("cp.async.wait_group 1;\n" ::: "memory")

__device__ __forceinline__ void ldsm_x4(uint32_t addr, uint32_t& r0, uint32_t& r1,
                                        uint32_t& r2, uint32_t& r3) {
    asm volatile("ldmatrix.sync.aligned.m8n8.x4.shared.b16 {%0,%1,%2,%3}, [%4];"
                 : "=r"(r0), "=r"(r1), "=r"(r2), "=r"(r3) : "r"(addr));
}

__device__ __forceinline__ void mma_16816(float* c, const uint32_t* a,
                                          uint32_t b0, uint32_t b1) {
    asm volatile(
        "mma.sync.aligned.m16n8k16.row.col.f32.f16.f16.f32 "
        "{%0,%1,%2,%3}, {%4,%5,%6,%7}, {%8,%9}, {%0,%1,%2,%3};"
        : "+f"(c[0]), "+f"(c[1]), "+f"(c[2]), "+f"(c[3])
        : "r"(a[0]), "r"(a[1]), "r"(a[2]), "r"(a[3]), "r"(b0), "r"(b1));
}

// ---------------- prepass 1: convert x -> fp16 ----------------
__global__ void __launch_bounds__(256) conv_x_kernel(const float4* __restrict__ x) {
    size_t i = (size_t)blockIdx.x * blockDim.x + threadIdx.x;  // 4 floats / thread
    float4 v = x[i];
    __half2* xp = reinterpret_cast<__half2*>(g_x);
    xp[2 * i]     = __floats2half2_rn(v.x, v.y);
    xp[2 * i + 1] = __floats2half2_rn(v.z, v.w);
}

// ---------------- prepass 2: transpose + convert w -> [n][k] fp16 ----------
__global__ void __launch_bounds__(256) conv_transpose_w_kernel(const float* __restrict__ w) {
    __shared__ float tile[32][33];
    int o0 = blockIdx.x * 32;  // output (N) tile
    int i0 = blockIdx.y * 32;  // input (K) tile
    int tx = threadIdx.x, ty = threadIdx.y;
    #pragma unroll
    for (int r = ty; r < 32; r += 8)
        tile[r][tx] = w[(size_t)(i0 + r) * NDIM + o0 + tx];
    __syncthreads();
    #pragma unroll
    for (int r = ty; r < 32; r += 8) {
        float f = tile[tx][r];  // = w[i0+tx][o0+r]
        g_w[(size_t)(o0 + r) * KDIM + i0 + tx] = __float2half_rn(f);
    }
}

// ---------------- producer: fill one pipeline stage ----------------
__device__ __forceinline__ void load_stage(uint32_t sb, int stage, int it,
                                           int m0, int n0, int tid) {
    int k0 = it * KC;
    uint32_t sa = sb + stage * STAGE_BYTES;
    uint32_t sbB = sa + TM * 128;
    // 256 rows * 8 segs of 16B = 2048 cp.async; 8 per thread
    #pragma unroll
    for (int j = 0; j < 8; ++j) {
        int t = tid + j * THREADS;
        int row = t >> 3;
        int seg = t & 7;
        if (row < TM) {
            const __half* gp = g_x + (size_t)(m0 + row) * KDIM + k0 + seg * 8;
            uint32_t sm = sa + row * 128 + ((seg ^ (row & 7)) << 4);
            cp_async16(sm, gp);
        } else {
            int rb = row - TM;
            const __half* gp = g_w + (size_t)(n0 + rb) * KDIM + k0 + seg * 8;
            uint32_t sm = sbB + rb * 128 + ((seg ^ (rb & 7)) << 4);
            cp_async16(sm, gp);
        }
    }
}

// ---------------- main GEMM: fp16 mma.sync, cp.async pipeline, 2 CTA/SM -----
__global__ void __launch_bounds__(THREADS, 2)
gemm_fp16_kernel(const float* __restrict__ bias, float* __restrict__ out) {
    extern __shared__ char smem[];
    uint32_t sb = smem_u32(smem);
    int tid = threadIdx.x;
    int lane = tid & 31;
    int wid = tid >> 5;
    int wm = wid & 1;       // M warp group (64 rows)
    int wn = wid >> 1;      // N warp group (32 cols)
    int m0 = blockIdx.y * TM;
    int n0 = blockIdx.x * TN;

    float acc[4][4][4];     // [mt 16-row tile][n8 tile][c0..c3]
    #pragma unroll
    for (int i = 0; i < 4; ++i)
        #pragma unroll
        for (int j = 0; j < 4; ++j)
            #pragma unroll
            for (int k = 0; k < 4; ++k) acc[i][j][k] = 0.f;

    // prologue: stages 0 and 1
    load_stage(sb, 0, 0, m0, n0, tid); CP_COMMIT();
    load_stage(sb, 1, 1, m0, n0, tid); CP_COMMIT();

    int la = (lane & 15);
    int khalf = lane >> 4;

    for (int it = 0; it < K_ITERS; ++it) {
        CP_WAIT1();
        __syncthreads();

        if (it + 2 < K_ITERS)
            load_stage(sb, (it + 2) % STAGES, it + 2, m0, n0, tid);
        CP_COMMIT();

        uint32_t sa = sb + (it % STAGES) * STAGE_BYTES;
        uint32_t sB = sa + TM * 128;

        #pragma unroll
        for (int ks = 0; ks < 4; ++ks) {
            int seg = 2 * ks + khalf;
            // A fragments: 4 m16 tiles
            uint32_t af[4][4];
            #pragma unroll
            for (int mt = 0; mt < 4; ++mt) {
                int row = wm * 64 + mt * 16 + la;
                uint32_t addr = sa + row * 128 + ((seg ^ (row & 7)) << 4);
                ldsm_x4(addr, af[mt][0], af[mt][1], af[mt][2], af[mt][3]);
            }
            // B fragments: 2 x4 loads cover 4 n8 tiles
            uint32_t bf[4][2];
            {
                int row = wn * 32 + la;
                uint32_t addr = sB + row * 128 + ((seg ^ (row & 7)) << 4);
                uint32_t r0, r1, r2, r3;
                ldsm_x4(addr, r0, r1, r2, r3);
                bf[0][0] = r0; bf[0][1] = r2;
                bf[1][0] = r1; bf[1][1] = r3;
                row = wn * 32 + 16 + la;
                addr = sB + row * 128 + ((seg ^ (row & 7)) << 4);
                ldsm_x4(addr, r0, r1, r2, r3);
                bf[2][0] = r0; bf[2][1] = r2;
                bf[3][0] = r1; bf[3][1] = r3;
            }
            #pragma unroll
            for (int mt = 0; mt < 4; ++mt)
                #pragma unroll
                for (int nb = 0; nb < 4; ++nb)
                    mma_16816(acc[mt][nb], af[mt], bf[nb][0], bf[nb][1]);
        }
    }

    // ---------------- epilogue: bias + store ----------------
    float2 bv[4];
    #pragma unroll
    for (int nb = 0; nb < 4; ++nb) {
        int col = n0 + wn * 32 + nb * 8 + (lane & 3) * 2;
        bv[nb] = *reinterpret_cast<const float2*>(bias + col);
    }
    #pragma unroll
    for (int mt = 0; mt < 4; ++mt) {
        int gr = m0 + wm * 64 + mt * 16 + (lane >> 2);
        float* r0p = out + (size_t)gr * NDIM;
        float* r1p = r0p + 8 * (size_t)NDIM;
        #pragma unroll
        for (int nb = 0; nb < 4; ++nb) {
            int col = n0 + wn * 32 + nb * 8 + (lane & 3) * 2;
            float2 v0 = make_float2(acc[mt][nb][0] + bv[nb].x,
                                    acc[mt][nb][1] + bv[nb].y);
            float2 v1 = make_float2(acc[mt][nb][2] + bv[nb].x,
                                    acc[mt][nb][3] + bv[nb].y);
            *reinterpret_cast<float2*>(r0p + col) = v0;
            *reinterpret_cast<float2*>(r1p + col) = v1;
        }
    }
}

// ---------------- launch ----------------
extern "C" void kernel_launch(void* const* d_in, const int* in_sizes, int n_in,
                              void* d_out, int out_size) {
    const float* x    = (const float*)d_in[0];
    const float* w    = (const float*)d_in[1];
    const float* bias = (const float*)d_in[2];
    float* out = (float*)d_out;

    conv_x_kernel<<<(BATCH * (size_t)KDIM / 4) / 256, 256>>>((const float4*)x);
    conv_transpose_w_kernel<<<dim3(NDIM / 32, KDIM / 32), dim3(32, 8)>>>(w);

    cudaFuncSetAttribute(gemm_fp16_kernel,
                         cudaFuncAttributeMaxDynamicSharedMemorySize, SMEM_TOTAL);
    gemm_fp16_kernel<<<dim3(NDIM / TN, BATCH / TM), THREADS, SMEM_TOTAL>>>(bias, out);
}